// round 6
// baseline (speedup 1.0000x reference)
#include <cuda_runtime.h>
#include <cstdint>
#include <cstddef>

#define NX  256
#define NU  32
#define NY  32
#define BB  16
#define TT  8192
#define LCH 128
#define NC  64        // TT / LCH
#define KTOT (NX + NU)    // 288: z rows + u rows
#define ZSTRIDE 132       // LCH + 4 pad (float4-aligned, banks shifted)
#define KSPLIT 144        // KTOT / 2

typedef unsigned long long ull;

// -------- scratch (allocation-free: __device__ globals) --------
__device__ float g_BzT[NU * NX];          // [u][n]
__device__ float g_CzT[NX * NY];          // [n][y]
__device__ float g_DT [NU * NY];          // [u][y]
__device__ float g_z0 [BB * NX];
__device__ float g_w  [BB * NC * NX];
__device__ float g_ss [BB * NC * NX];
__device__ float g_v  [(size_t)BB * TT * NX];   // 128 MB

// -------- f32x2 helpers --------
__device__ __forceinline__ void ffma2(ull& d, ull a, ull b) {
    asm("fma.rn.f32x2 %0, %1, %2, %0;" : "+l"(d) : "l"(a), "l"(b));
}
__device__ __forceinline__ ull addf2(ull a, ull b) {
    ull r; asm("add.rn.f32x2 %0, %1, %2;" : "=l"(r) : "l"(a), "l"(b)); return r;
}
__device__ __forceinline__ ull dup2(float x) {
    ull r; asm("mov.b64 %0, {%1, %1};" : "=l"(r) : "f"(x)); return r;
}
__device__ __forceinline__ ull pack2(float lo, float hi) {
    ull r; asm("mov.b64 %0, {%1, %2};" : "=l"(r) : "f"(lo), "f"(hi)); return r;
}
__device__ __forceinline__ float2 unpk(ull a) {
    float2 f; asm("mov.b64 {%0, %1}, %2;" : "=f"(f.x), "=f"(f.y) : "l"(a)); return f;
}
union F4U2 { float4 f; ull u[2]; };

// -------- prep --------
__global__ __launch_bounds__(256) void prep_kernel(
    const float* __restrict__ x0, const float* __restrict__ Q,
    const float* __restrict__ Bmat, const float* __restrict__ C,
    const float* __restrict__ D)
{
    int idx = blockIdx.x * 256 + threadIdx.x;
    if (idx < NU * NX) {
        int u = idx >> 8, n = idx & 255;
        float a = 0.f;
        #pragma unroll 8
        for (int i = 0; i < NX; i++) a = fmaf(Q[i * NX + n], Bmat[i * NU + u], a);
        g_BzT[u * NX + n] = a;
    } else if (idx < NU * NX + NY * NX) {
        int j = idx - NU * NX;
        int y = j >> 8, n = j & 255;
        float a = 0.f;
        #pragma unroll 8
        for (int i = 0; i < NX; i++) a = fmaf(C[y * NX + i], Q[i * NX + n], a);
        g_CzT[n * NY + y] = a;
    } else if (idx < NU * NX + NY * NX + BB * NX) {
        int j = idx - NU * NX - NY * NX;
        int b = j >> 8, n = j & 255;
        float a = 0.f;
        #pragma unroll 8
        for (int i = 0; i < NX; i++) a = fmaf(x0[b * NX + i], Q[i * NX + n], a);
        g_z0[b * NX + n] = a;
    } else if (idx < NU * NX + NY * NX + BB * NX + NU * NY) {
        int j = idx - NU * NX - NY * NX - BB * NX;
        int u = j >> 5, y = j & 31;
        g_DT[u * NY + y] = D[y * NU + u];
    }
}

// -------- pass1: v = Bz u (stored) + Horner sums, f32x2 inner --------
__global__ __launch_bounds__(256) void pass1_kernel(
    const float* __restrict__ u, const float* __restrict__ lam)
{
    int b = blockIdx.x >> 6;
    int c = blockIdx.x & (NC - 1);
    int n = threadIdx.x;

    __shared__ float s_u[LCH * NU];

    const float4* up4 = (const float4*)(u + ((size_t)b * TT + (size_t)c * LCH) * NU);
    float4* su4 = (float4*)s_u;
    #pragma unroll
    for (int i = 0; i < (LCH * NU / 4) / 256; i++)
        su4[n + i * 256] = up4[n + i * 256];

    ull bzp[NU / 2];                      // packed Bz row pairs
    #pragma unroll
    for (int k = 0; k < NU / 2; k++)
        bzp[k] = pack2(g_BzT[(2 * k) * NX + n], g_BzT[(2 * k + 1) * NX + n]);
    float lamn = lam[n];
    __syncthreads();

    float w = 0.f;
    float* vout = g_v + ((size_t)b * TT + (size_t)c * LCH) * NX + n;
    #pragma unroll 2
    for (int j = 0; j < LCH; j++) {
        const float4* uu = (const float4*)(s_u + j * NU);
        ull a0 = 0, a1 = 0, a2 = 0, a3 = 0;
        #pragma unroll
        for (int k4 = 0; k4 < 8; k4++) {
            F4U2 q; q.f = uu[k4];
            if (k4 & 1) { ffma2(a2, bzp[2 * k4], q.u[0]); ffma2(a3, bzp[2 * k4 + 1], q.u[1]); }
            else        { ffma2(a0, bzp[2 * k4], q.u[0]); ffma2(a1, bzp[2 * k4 + 1], q.u[1]); }
        }
        a0 = addf2(a0, a2); a1 = addf2(a1, a3); a0 = addf2(a0, a1);
        float2 f = unpk(a0);
        float v = f.x + f.y;
        w = fmaf(lamn, w, v);
        vout[(size_t)j * NX] = v;
    }
    g_w[((size_t)b * NC + c) * NX + n] = w;
}

// -------- chunkscan --------
__global__ __launch_bounds__(256) void chunkscan_kernel(const float* __restrict__ lam)
{
    int b = blockIdx.x;
    int n = threadIdx.x;
    float lamL = lam[n];
    #pragma unroll
    for (int i = 0; i < 7; i++) lamL *= lamL;   // lam^128
    float s = g_z0[b * NX + n];
    const size_t base = (size_t)b * NC * NX + n;
    for (int cg = 0; cg < NC / 16; cg++) {
        float wv[16];
        #pragma unroll
        for (int i = 0; i < 16; i++)
            wv[i] = g_w[base + (size_t)(cg * 16 + i) * NX];
        #pragma unroll
        for (int i = 0; i < 16; i++) {
            g_ss[base + (size_t)(cg * 16 + i) * NX] = s;
            s = fmaf(lamL, s, wv[i]);
        }
    }
}

// -------- pass3: scan -> smem Z, then register-tiled f32x2 GEMM --------
// smem: ZT[KTOT][ZSTRIDE] (z states + u^T), W[KTOT][NY] ([Cz;D]), red[4096]
#define SM_ZT 0
#define SM_W  (KTOT * ZSTRIDE)                  // 38016
#define SM_RED (SM_W + KTOT * NY)               // 47232
#define SM_FLOATS (SM_RED + LCH * NY)           // 51328 -> 205312 B

__global__ __launch_bounds__(512, 1) void pass3_kernel(
    const float* __restrict__ u, const float* __restrict__ lam,
    float* __restrict__ y)
{
    extern __shared__ float sm[];
    float* ZT  = sm + SM_ZT;
    float* Wm  = sm + SM_W;
    float* red = sm + SM_RED;

    int b   = blockIdx.x >> 6;
    int c   = blockIdx.x & (NC - 1);
    int tid = threadIdx.x;
    const size_t chunk = (size_t)b * TT + (size_t)c * LCH;

    if (tid < NX) {
        // ---- scan: this thread owns mode tid ----
        float lamn = lam[tid];
        float smy  = g_ss[((size_t)b * NC + c) * NX + tid];
        const float* vp = g_v + chunk * NX + tid;
        float* zr = ZT + tid * ZSTRIDE;

        float vb[16];
        #pragma unroll
        for (int i = 0; i < 16; i++) vb[i] = vp[(size_t)i * NX];
        for (int grp = 0; grp < 8; grp++) {
            float vb2[16];
            if (grp < 7) {
                #pragma unroll
                for (int i = 0; i < 16; i++)
                    vb2[i] = vp[(size_t)(16 * (grp + 1) + i) * NX];
            }
            #pragma unroll
            for (int i = 0; i < 16; i++) {
                zr[16 * grp + i] = smy;              // state BEFORE step
                smy = fmaf(lamn, smy, vb[i]);
            }
            #pragma unroll
            for (int i = 0; i < 16; i++) vb[i] = vb2[i];
        }
    } else {
        // ---- helpers: u^T into ZT rows 256.., and W = [Cz; D] ----
        int t2 = tid - NX;
        const float* ub = u + chunk * NU;
        #pragma unroll
        for (int i = 0; i < 16; i++) {
            int e = t2 + i * 256;                    // coalesced
            int t = e >> 5, uu = e & 31;
            ZT[(NX + uu) * ZSTRIDE + t] = ub[e];
        }
        for (int i = t2; i < KTOT * NY; i += 256)
            Wm[i] = (i < NX * NY) ? g_CzT[i] : g_DT[i - NX * NY];
    }
    __syncthreads();

    // ---- GEMM: Y[t][y] = sum_k ZT[k][t] * W[k][y], K-split over 2 halves ----
    int ks = tid >> 8;          // 0: k in [0,144), 1: k in [144,288)
    int r  = tid & 255;
    int yg = r >> 5;            // y tile = [4yg, 4yg+4)
    int tg = r & 31;            // t tile = [4tg, 4tg+4)

    ull acc[2][4];              // [t-pair][y]
    #pragma unroll
    for (int i = 0; i < 2; i++)
        #pragma unroll
        for (int j = 0; j < 4; j++) acc[i][j] = 0;

    const float* zp = ZT + ks * KSPLIT * ZSTRIDE + 4 * tg;
    const float* wp = Wm + ks * KSPLIT * NY + 4 * yg;
    #pragma unroll 4
    for (int k = 0; k < KSPLIT; k++) {
        F4U2 z; z.f = *(const float4*)(zp + k * ZSTRIDE);
        float4 wv = *(const float4*)(wp + k * NY);
        ull b0 = dup2(wv.x), b1 = dup2(wv.y), b2 = dup2(wv.z), b3 = dup2(wv.w);
        ffma2(acc[0][0], z.u[0], b0); ffma2(acc[1][0], z.u[1], b0);
        ffma2(acc[0][1], z.u[0], b1); ffma2(acc[1][1], z.u[1], b1);
        ffma2(acc[0][2], z.u[0], b2); ffma2(acc[1][2], z.u[1], b2);
        ffma2(acc[0][3], z.u[0], b3); ffma2(acc[1][3], z.u[1], b3);
    }

    // ---- combine halves: ks=1 stages partials, ks=0 adds + stores ----
    if (ks == 1) {
        float* rr = red + r * 16;
        #pragma unroll
        for (int tp = 0; tp < 2; tp++)
            #pragma unroll
            for (int j = 0; j < 4; j++) {
                float2 f = unpk(acc[tp][j]);
                rr[tp * 8 + j * 2 + 0] = f.x;
                rr[tp * 8 + j * 2 + 1] = f.y;
            }
    }
    __syncthreads();
    if (ks == 0) {
        const float* rr = red + r * 16;
        float* yp = y + chunk * NY;
        #pragma unroll
        for (int tp = 0; tp < 2; tp++) {
            float2 f0 = unpk(acc[tp][0]), f1 = unpk(acc[tp][1]);
            float2 f2 = unpk(acc[tp][2]), f3 = unpk(acc[tp][3]);
            float4 lo, hi;
            lo.x = f0.x + rr[tp * 8 + 0]; lo.y = f1.x + rr[tp * 8 + 2];
            lo.z = f2.x + rr[tp * 8 + 4]; lo.w = f3.x + rr[tp * 8 + 6];
            hi.x = f0.y + rr[tp * 8 + 1]; hi.y = f1.y + rr[tp * 8 + 3];
            hi.z = f2.y + rr[tp * 8 + 5]; hi.w = f3.y + rr[tp * 8 + 7];
            int t0 = 4 * tg + 2 * tp;
            *(float4*)(yp + (size_t)t0 * NY + 4 * yg)       = lo;
            *(float4*)(yp + (size_t)(t0 + 1) * NY + 4 * yg) = hi;
        }
    }
}

// -------- launch --------
extern "C" void kernel_launch(void* const* d_in, const int* in_sizes, int n_in,
                              void* d_out, int out_size)
{
    const float* x0   = (const float*)d_in[0];
    const float* u    = (const float*)d_in[1];
    const float* Q    = (const float*)d_in[2];
    const float* lam  = (const float*)d_in[3];
    const float* Bmat = (const float*)d_in[4];
    const float* C    = (const float*)d_in[5];
    const float* D    = (const float*)d_in[6];
    float* y = (float*)d_out;
    (void)in_sizes; (void)n_in; (void)out_size;

    cudaFuncSetAttribute(pass3_kernel,
                         cudaFuncAttributeMaxDynamicSharedMemorySize,
                         SM_FLOATS * (int)sizeof(float));

    prep_kernel<<<84, 256>>>(x0, Q, Bmat, C, D);
    pass1_kernel<<<BB * NC, 256>>>(u, lam);
    chunkscan_kernel<<<BB, 256>>>(lam);
    pass3_kernel<<<BB * NC, 512, SM_FLOATS * sizeof(float)>>>(u, lam, y);
}